// round 4
// baseline (speedup 1.0000x reference)
#include <cuda_runtime.h>

#define BB 16
#define CC 1024
#define NLOC 3136            // 16*14*14
#define N4 (NLOC / 4)        // 784
#define CSPLIT 16
#define CCHUNK (CC / CSPLIT) // 64
#define MARGIN 0.2f
#define INV_TEMP 1000.0f
#define SCALE 100000.0f

__device__ float4 g_pp[BB * CSPLIT * N4];   // posdot partials
__device__ float4 g_np[BB * CSPLIT * N4];   // negdot partials
__device__ float4 g_pd[BB * N4];            // reduced posdot
__device__ float4 g_nd[BB * N4];            // reduced negdot

// ---------------------------------------------------------------------------
// Kernel 1: fused batched matvec, C split 16-ways, float4 streaming loads.
// grid = (7, 16, 16) = 1792 blocks, block = 128
// ---------------------------------------------------------------------------
__global__ void __launch_bounds__(128)
dot_kernel(const float* __restrict__ ft,
           const float* __restrict__ pos,
           const float* __restrict__ neg)
{
    __shared__ float s_pos[CCHUNK];
    __shared__ float s_neg[CCHUNK];
    const int b  = blockIdx.z;
    const int cs = blockIdx.y;
    const int c0 = cs * CCHUNK;

    if (threadIdx.x < CCHUNK) {
        s_pos[threadIdx.x] = pos[b * CC + c0 + threadIdx.x];
        s_neg[threadIdx.x] = neg[b * CC + c0 + threadIdx.x];
    }
    __syncthreads();

    const int n4 = blockIdx.x * blockDim.x + threadIdx.x;
    if (n4 >= N4) return;

    const float4* base = (const float4*)(ft + (size_t)b * CC * NLOC
                                            + (size_t)c0 * NLOC) + n4;
    float4 pd = {0.f, 0.f, 0.f, 0.f};
    float4 nd = {0.f, 0.f, 0.f, 0.f};

#pragma unroll 16
    for (int c = 0; c < CCHUNK; ++c) {
        float4 v = __ldcs(base + (size_t)c * N4);   // streaming: evict-first
        float sp = s_pos[c], sn = s_neg[c];
        pd.x = fmaf(v.x, sp, pd.x);  pd.y = fmaf(v.y, sp, pd.y);
        pd.z = fmaf(v.z, sp, pd.z);  pd.w = fmaf(v.w, sp, pd.w);
        nd.x = fmaf(v.x, sn, nd.x);  nd.y = fmaf(v.y, sn, nd.y);
        nd.z = fmaf(v.z, sn, nd.z);  nd.w = fmaf(v.w, sn, nd.w);
    }

    const int idx = (b * CSPLIT + cs) * N4 + n4;
    g_pp[idx] = pd;
    g_np[idx] = nd;
}

// ---------------------------------------------------------------------------
// Kernel 2: wide partial-reduce (12.8 MB -> 0.8 MB), L2-resident.
// Also zero-initializes the loss accumulator slot in d_out.
// grid = 98 blocks, block = 128.
// ---------------------------------------------------------------------------
__global__ void __launch_bounds__(128)
reduce_kernel(float* __restrict__ out, int out_size)
{
    const int idx = blockIdx.x * blockDim.x + threadIdx.x;
    if (idx == 0 && out_size > BB * NLOC) out[BB * NLOC] = 0.0f;
    if (idx >= BB * N4) return;
    const int b  = idx / N4;
    const int n4 = idx - b * N4;

    float4 pd = {0.f, 0.f, 0.f, 0.f};
    float4 nd = {0.f, 0.f, 0.f, 0.f};
#pragma unroll
    for (int cs = 0; cs < CSPLIT; ++cs) {
        float4 p = g_pp[(b * CSPLIT + cs) * N4 + n4];
        float4 q = g_np[(b * CSPLIT + cs) * N4 + n4];
        pd.x += p.x; pd.y += p.y; pd.z += p.z; pd.w += p.w;
        nd.x += q.x; nd.y += q.y; nd.z += q.z; nd.w += q.w;
    }
    g_pd[idx] = pd;
    g_nd[idx] = nd;
}

// ---------------------------------------------------------------------------
// Kernel 3: per-batch softmax + margin loss, loss accumulated into out[B*N].
// grid = BB, block = 1024. Row lives in registers (tid < 784 active).
// ---------------------------------------------------------------------------
__global__ void __launch_bounds__(1024)
softmax_loss_kernel(float* __restrict__ out, int out_size)
{
    const int b   = blockIdx.x;
    const int tid = threadIdx.x;
    __shared__ float red[32];
    const bool act = tid < N4;

    float4 pd = {-1e30f, -1e30f, -1e30f, -1e30f};
    float4 nd = {0.f, 0.f, 0.f, 0.f};
    if (act) {
        pd = g_pd[b * N4 + tid];
        nd = g_nd[b * N4 + tid];
    }

    // ---- block max ----
    float m = fmaxf(fmaxf(pd.x, pd.y), fmaxf(pd.z, pd.w));
#pragma unroll
    for (int o = 16; o > 0; o >>= 1)
        m = fmaxf(m, __shfl_xor_sync(0xffffffffu, m, o));
    if ((tid & 31) == 0) red[tid >> 5] = m;
    __syncthreads();
    if (tid < 32) {
        float v = red[tid];
#pragma unroll
        for (int o = 16; o > 0; o >>= 1)
            v = fmaxf(v, __shfl_xor_sync(0xffffffffu, v, o));
        if (tid == 0) red[0] = v;
    }
    __syncthreads();
    const float mx = red[0];
    __syncthreads();

    // ---- exp + block sum ----
    float4 e = {0.f, 0.f, 0.f, 0.f};
    if (act) {
        e.x = expf((pd.x - mx) * INV_TEMP);
        e.y = expf((pd.y - mx) * INV_TEMP);
        e.z = expf((pd.z - mx) * INV_TEMP);
        e.w = expf((pd.w - mx) * INV_TEMP);
    }
    float s = e.x + e.y + e.z + e.w;
#pragma unroll
    for (int o = 16; o > 0; o >>= 1)
        s += __shfl_xor_sync(0xffffffffu, s, o);
    if ((tid & 31) == 0) red[tid >> 5] = s;
    __syncthreads();
    if (tid < 32) {
        float v = red[tid];
#pragma unroll
        for (int o = 16; o > 0; o >>= 1)
            v += __shfl_xor_sync(0xffffffffu, v, o);
        if (tid == 0) red[0] = v;
    }
    __syncthreads();
    const float invZ = 1.0f / red[0];
    __syncthreads();

    // ---- attn write + loss partial ----
    float l = 0.0f;
    if (act) {
        float4 a;
        a.x = e.x * invZ;  a.y = e.y * invZ;
        a.z = e.z * invZ;  a.w = e.w * invZ;
        ((float4*)(out + b * NLOC))[tid] = a;
        l = fmaf(fmaxf(MARGIN + (nd.x - pd.x) * SCALE, 0.0f), a.x, l);
        l = fmaf(fmaxf(MARGIN + (nd.y - pd.y) * SCALE, 0.0f), a.y, l);
        l = fmaf(fmaxf(MARGIN + (nd.z - pd.z) * SCALE, 0.0f), a.z, l);
        l = fmaf(fmaxf(MARGIN + (nd.w - pd.w) * SCALE, 0.0f), a.w, l);
    }
#pragma unroll
    for (int o = 16; o > 0; o >>= 1)
        l += __shfl_xor_sync(0xffffffffu, l, o);
    if ((tid & 31) == 0) red[tid >> 5] = l;
    __syncthreads();
    if (tid < 32) {
        float v = red[tid];
#pragma unroll
        for (int o = 16; o > 0; o >>= 1)
            v += __shfl_xor_sync(0xffffffffu, v, o);
        if (tid == 0 && out_size > BB * NLOC)
            atomicAdd(out + BB * NLOC, v * (1.0f / (float)BB));
    }
}

extern "C" void kernel_launch(void* const* d_in, const int* in_sizes, int n_in,
                              void* d_out, int out_size)
{
    const float* ft  = (const float*)d_in[0];
    const float* pos = (const float*)d_in[1];
    const float* neg = (const float*)d_in[2];
    float* out = (float*)d_out;

    dim3 grid1((N4 + 127) / 128, CSPLIT, BB);
    dot_kernel<<<grid1, 128>>>(ft, pos, neg);

    reduce_kernel<<<(BB * N4 + 127) / 128, 128>>>(out, out_size);

    softmax_loss_kernel<<<BB, 1024>>>(out, out_size);
}

// round 5
// speedup vs baseline: 1.1104x; 1.1104x over previous
#include <cuda_runtime.h>

#define BB 16
#define CC 1024
#define NLOC 3136            // 16*14*14
#define N4 (NLOC / 4)        // 784
#define CSPLIT 16
#define CCHUNK (CC / CSPLIT) // 64
#define MARGIN 0.2f
#define INV_TEMP 1000.0f
#define SCALE 100000.0f

__device__ float4 g_pp[BB * CSPLIT * N4];   // posdot partials
__device__ float4 g_np[BB * CSPLIT * N4];   // negdot partials

// ---------------------------------------------------------------------------
// Kernel 1: fused batched matvec, C split 16-ways, float4 loads.
// grid = (7, 16, 16) = 1792 blocks, block = 128
// Also zero-initializes the loss slot (runs before the epilogue kernel).
// ---------------------------------------------------------------------------
__global__ void __launch_bounds__(128)
dot_kernel(const float* __restrict__ ft,
           const float* __restrict__ pos,
           const float* __restrict__ neg,
           float* __restrict__ out, int out_size)
{
    __shared__ float s_pos[CCHUNK];
    __shared__ float s_neg[CCHUNK];
    const int b  = blockIdx.z;
    const int cs = blockIdx.y;
    const int c0 = cs * CCHUNK;

    if (blockIdx.x == 0 && blockIdx.y == 0 && blockIdx.z == 0 &&
        threadIdx.x == 0 && out_size > BB * NLOC)
        out[BB * NLOC] = 0.0f;

    if (threadIdx.x < CCHUNK) {
        s_pos[threadIdx.x] = pos[b * CC + c0 + threadIdx.x];
        s_neg[threadIdx.x] = neg[b * CC + c0 + threadIdx.x];
    }
    __syncthreads();

    const int n4 = blockIdx.x * blockDim.x + threadIdx.x;
    if (n4 >= N4) return;

    const float4* base = (const float4*)(ft + (size_t)b * CC * NLOC
                                            + (size_t)c0 * NLOC) + n4;
    float4 pd = {0.f, 0.f, 0.f, 0.f};
    float4 nd = {0.f, 0.f, 0.f, 0.f};

#pragma unroll 8
    for (int c = 0; c < CCHUNK; ++c) {
        float4 v = __ldg(base + (size_t)c * N4);
        float sp = s_pos[c], sn = s_neg[c];
        pd.x = fmaf(v.x, sp, pd.x);  pd.y = fmaf(v.y, sp, pd.y);
        pd.z = fmaf(v.z, sp, pd.z);  pd.w = fmaf(v.w, sp, pd.w);
        nd.x = fmaf(v.x, sn, nd.x);  nd.y = fmaf(v.y, sn, nd.y);
        nd.z = fmaf(v.z, sn, nd.z);  nd.w = fmaf(v.w, sn, nd.w);
    }

    const int idx = (b * CSPLIT + cs) * N4 + n4;
    g_pp[idx] = pd;
    g_np[idx] = nd;
}

// ---------------------------------------------------------------------------
// Kernel 2 (fused epilogue): per-batch partial-reduce + softmax + margin loss.
// grid = BB = 16 blocks, block = 1024. Row lives in registers (tid < 784).
// Loss accumulated into out[B*NLOC] via atomicAdd (zeroed by dot_kernel).
// ---------------------------------------------------------------------------
__global__ void __launch_bounds__(1024)
epilogue_kernel(float* __restrict__ out, int out_size)
{
    const int b   = blockIdx.x;
    const int tid = threadIdx.x;
    __shared__ float red[32];
    const bool act = tid < N4;

    // ---- reduce CSPLIT partials straight into registers ----
    float4 pd = {-1e30f, -1e30f, -1e30f, -1e30f};
    float4 nd = {0.f, 0.f, 0.f, 0.f};
    if (act) {
        pd.x = pd.y = pd.z = pd.w = 0.f;
#pragma unroll
        for (int cs = 0; cs < CSPLIT; ++cs) {
            float4 p = g_pp[(b * CSPLIT + cs) * N4 + tid];
            float4 q = g_np[(b * CSPLIT + cs) * N4 + tid];
            pd.x += p.x; pd.y += p.y; pd.z += p.z; pd.w += p.w;
            nd.x += q.x; nd.y += q.y; nd.z += q.z; nd.w += q.w;
        }
    }

    // ---- block max ----
    float m = act ? fmaxf(fmaxf(pd.x, pd.y), fmaxf(pd.z, pd.w)) : -1e30f;
#pragma unroll
    for (int o = 16; o > 0; o >>= 1)
        m = fmaxf(m, __shfl_xor_sync(0xffffffffu, m, o));
    if ((tid & 31) == 0) red[tid >> 5] = m;
    __syncthreads();
    if (tid < 32) {
        float v = red[tid];
#pragma unroll
        for (int o = 16; o > 0; o >>= 1)
            v = fmaxf(v, __shfl_xor_sync(0xffffffffu, v, o));
        if (tid == 0) red[0] = v;
    }
    __syncthreads();
    const float mx = red[0];
    __syncthreads();

    // ---- exp + block sum ----
    float4 e = {0.f, 0.f, 0.f, 0.f};
    if (act) {
        e.x = expf((pd.x - mx) * INV_TEMP);
        e.y = expf((pd.y - mx) * INV_TEMP);
        e.z = expf((pd.z - mx) * INV_TEMP);
        e.w = expf((pd.w - mx) * INV_TEMP);
    }
    float s = e.x + e.y + e.z + e.w;
#pragma unroll
    for (int o = 16; o > 0; o >>= 1)
        s += __shfl_xor_sync(0xffffffffu, s, o);
    if ((tid & 31) == 0) red[tid >> 5] = s;
    __syncthreads();
    if (tid < 32) {
        float v = red[tid];
#pragma unroll
        for (int o = 16; o > 0; o >>= 1)
            v += __shfl_xor_sync(0xffffffffu, v, o);
        if (tid == 0) red[0] = v;
    }
    __syncthreads();
    const float invZ = 1.0f / red[0];
    __syncthreads();

    // ---- attn write + loss partial ----
    float l = 0.0f;
    if (act) {
        float4 a;
        a.x = e.x * invZ;  a.y = e.y * invZ;
        a.z = e.z * invZ;  a.w = e.w * invZ;
        ((float4*)(out + b * NLOC))[tid] = a;
        l = fmaf(fmaxf(MARGIN + (nd.x - pd.x) * SCALE, 0.0f), a.x, l);
        l = fmaf(fmaxf(MARGIN + (nd.y - pd.y) * SCALE, 0.0f), a.y, l);
        l = fmaf(fmaxf(MARGIN + (nd.z - pd.z) * SCALE, 0.0f), a.z, l);
        l = fmaf(fmaxf(MARGIN + (nd.w - pd.w) * SCALE, 0.0f), a.w, l);
    }
#pragma unroll
    for (int o = 16; o > 0; o >>= 1)
        l += __shfl_xor_sync(0xffffffffu, l, o);
    if ((tid & 31) == 0) red[tid >> 5] = l;
    __syncthreads();
    if (tid < 32) {
        float v = red[tid];
#pragma unroll
        for (int o = 16; o > 0; o >>= 1)
            v += __shfl_xor_sync(0xffffffffu, v, o);
        if (tid == 0 && out_size > BB * NLOC)
            atomicAdd(out + BB * NLOC, v * (1.0f / (float)BB));
    }
}

extern "C" void kernel_launch(void* const* d_in, const int* in_sizes, int n_in,
                              void* d_out, int out_size)
{
    const float* ft  = (const float*)d_in[0];
    const float* pos = (const float*)d_in[1];
    const float* neg = (const float*)d_in[2];
    float* out = (float*)d_out;

    dim3 grid1((N4 + 127) / 128, CSPLIT, BB);
    dot_kernel<<<grid1, 128>>>(ft, pos, neg, out, out_size);

    epilogue_kernel<<<BB, 1024>>>(out, out_size);
}